// round 15
// baseline (speedup 1.0000x reference)
#include <cuda_runtime.h>
#include <stdint.h>

// Segmented max pooling — bucketed gather (converged R9 configuration; the
// zero pass is a single cudaMemsetAsync over a merged counts+spill region):
//   1) memset: counts + spill counter (1 MB, driver memset)
//   2) fill:   pos = atomicAdd(count[seg]); pos<CAP -> bucket, else spill list
//   3) gather: 1 warp per 2 segments, batched predicated loads (MLP=8),
//              int4 bucket index loads, inline spill scan.
//
// MEASURED LESSONS (guardrails):
//  - No single-address done-counter atomic across the big grid
//    (R6/R7: +400us, LTS same-address convoy).
//  - Plain __ldg loads (R5/R8/R9 good); no .cs hints.
//  - MLP=8 (2 segs/warp, 256 TPB) is the sweet spot: MLP=16 regressed (R10),
//    512 TPB + in-gather count reset regressed (R11), int2 counts neutral
//    (R12), peeled first iteration regressed (R13).
//  - Launch floor ~3.7us/kernel: 3 stream ops is the practical minimum.
// Fallback: generic atomic-scatter path for shapes beyond static scratch.

#define MAX_SEG   (1 << 18)   // 262144
#define MAX_ROWS  (1 << 20)   // 1048576
#define CAP        16
#define NEG_INF __int_as_float(0xff800000)

// counts[0..MAX_SEG) and the spill counter share one array so a single
// cudaMemsetAsync clears both. Slot MAX_SEG = spill counter (padded to 32
// words to keep the memset size 128B-aligned).
__device__ int g_meta[MAX_SEG + 32];
#define g_counts g_meta
#define SPILL_IDX MAX_SEG

__device__ int g_bucket[MAX_SEG * CAP];   // 16 MB scratch
__device__ int g_spill_rows[MAX_ROWS];

// ---------------- bucketed gather path ----------------

__global__ void fill_kernel(const int4* __restrict__ vt_map4, int n_rows4, int vt_out) {
    int i = blockIdx.x * blockDim.x + threadIdx.x;
    if (i >= n_rows4) return;
    int4 m = __ldg(&vt_map4[i]);
    int rows[4] = {4 * i, 4 * i + 1, 4 * i + 2, 4 * i + 3};
    int segs[4] = {m.x, m.y, m.z, m.w};
    #pragma unroll
    for (int k = 0; k < 4; k++) {
        int seg = segs[k];
        if (seg < 0 || seg >= vt_out) continue;
        int pos = atomicAdd(&g_counts[seg], 1);
        if (pos < CAP) {
            g_bucket[(size_t)seg * CAP + pos] = rows[k];
        } else {
            int s = atomicAdd(&g_counts[SPILL_IDX], 1);
            g_spill_rows[s] = rows[k];
        }
    }
}

__device__ __forceinline__ void spill_scan(float2& acc, int seg, int lane,
                                           const float2* __restrict__ in2,
                                           const int* __restrict__ vt_map) {
    int sn = g_counts[SPILL_IDX];
    for (int e = 0; e < sn; e++) {
        int row = g_spill_rows[e];
        if (__ldg(&vt_map[row]) == seg) {
            float2 a = __ldg(&in2[(size_t)row * 32 + lane]);
            acc.x = fmaxf(acc.x, a.x);
            acc.y = fmaxf(acc.y, a.y);
        }
    }
}

// One warp per TWO segments; C == 64: lane holds channels {2l, 2l+1} (float2).
// All 8 row loads per iteration are issued before any max consumes them.
__global__ void gather_max_kernel(const float2* __restrict__ in2,
                                  const int* __restrict__ vt_map,
                                  float2* __restrict__ out2, int nseg) {
    int warp = (blockIdx.x * blockDim.x + threadIdx.x) >> 5;
    int lane = threadIdx.x & 31;
    int s0 = 2 * warp;
    int s1 = s0 + 1;
    if (s0 >= nseg) return;
    bool has1 = (s1 < nseg);

    int cnt0 = __ldg(&g_counts[s0]);
    int cnt1 = has1 ? __ldg(&g_counts[s1]) : 0;
    int use0 = cnt0 < CAP ? cnt0 : CAP;
    int use1 = cnt1 < CAP ? cnt1 : CAP;

    const int4* __restrict__ b0 = (const int4*)(g_bucket + (size_t)s0 * CAP);
    const int4* __restrict__ b1 = (const int4*)(g_bucket + (size_t)s1 * CAP);

    float2 a0 = make_float2(NEG_INF, NEG_INF);
    float2 a1 = make_float2(NEG_INF, NEG_INF);
    const float2 ninf2 = make_float2(NEG_INF, NEG_INF);

    int usemax = use0 > use1 ? use0 : use1;
    for (int j = 0; j < usemax; j += 4) {
        int4 i0 = (j < use0) ? __ldg(&b0[j >> 2]) : make_int4(0, 0, 0, 0);
        int4 i1 = (j < use1) ? __ldg(&b1[j >> 2]) : make_int4(0, 0, 0, 0);

        // Issue all row loads first (predicated; NEG_INF is max-identity).
        float2 v00 = ninf2, v01 = ninf2, v02 = ninf2, v03 = ninf2;
        float2 v10 = ninf2, v11 = ninf2, v12 = ninf2, v13 = ninf2;
        if (j + 0 < use0) v00 = __ldg(&in2[(size_t)i0.x * 32 + lane]);
        if (j + 1 < use0) v01 = __ldg(&in2[(size_t)i0.y * 32 + lane]);
        if (j + 2 < use0) v02 = __ldg(&in2[(size_t)i0.z * 32 + lane]);
        if (j + 3 < use0) v03 = __ldg(&in2[(size_t)i0.w * 32 + lane]);
        if (j + 0 < use1) v10 = __ldg(&in2[(size_t)i1.x * 32 + lane]);
        if (j + 1 < use1) v11 = __ldg(&in2[(size_t)i1.y * 32 + lane]);
        if (j + 2 < use1) v12 = __ldg(&in2[(size_t)i1.z * 32 + lane]);
        if (j + 3 < use1) v13 = __ldg(&in2[(size_t)i1.w * 32 + lane]);

        a0.x = fmaxf(fmaxf(a0.x, fmaxf(v00.x, v01.x)), fmaxf(v02.x, v03.x));
        a0.y = fmaxf(fmaxf(a0.y, fmaxf(v00.y, v01.y)), fmaxf(v02.y, v03.y));
        a1.x = fmaxf(fmaxf(a1.x, fmaxf(v10.x, v11.x)), fmaxf(v12.x, v13.x));
        a1.y = fmaxf(fmaxf(a1.y, fmaxf(v10.y, v11.y)), fmaxf(v12.y, v13.y));
    }

    if (cnt0 > CAP) spill_scan(a0, s0, lane, in2, vt_map);   // statistically never
    if (cnt1 > CAP) spill_scan(a1, s1, lane, in2, vt_map);

    if (cnt0 == 0) a0 = make_float2(0.0f, 0.0f);
    if (cnt1 == 0) a1 = make_float2(0.0f, 0.0f);

    out2[(size_t)s0 * 32 + lane] = a0;
    if (has1) out2[(size_t)s1 * 32 + lane] = a1;
}

// ---------------- fallback scatter path (generic) ----------------

__device__ __forceinline__ unsigned fkey(float f) {
    unsigned b = __float_as_uint(f);
    return (b & 0x80000000u) ? ~b : (b | 0x80000000u);
}
__device__ __forceinline__ float fdecode(unsigned k) {
    unsigned b = (k & 0x80000000u) ? (k & 0x7FFFFFFFu) : ~k;
    return __uint_as_float(b);
}
#define INIT_KEY 0x007FFFFFu

__global__ void init_out_kernel(unsigned* out, long n) {
    long i = blockIdx.x * (long)blockDim.x + threadIdx.x;
    long stride = gridDim.x * (long)blockDim.x;
    for (; i < n; i += stride) out[i] = INIT_KEY;
}

__global__ void scatter_max_kernel(const float* __restrict__ in,
                                   const int* __restrict__ vt_map,
                                   unsigned* __restrict__ out,
                                   long n_total, int C, int vt_out) {
    long i = blockIdx.x * (long)blockDim.x + threadIdx.x;
    long stride = gridDim.x * (long)blockDim.x;
    for (; i < n_total; i += stride) {
        long row = i / C;
        int  c   = (int)(i - row * C);
        int seg = vt_map[row];
        if (seg < 0 || seg >= vt_out) continue;
        atomicMax(out + (size_t)seg * C + c, fkey(in[i]));
    }
}

__global__ void fixup_kernel(unsigned* __restrict__ out, long n) {
    long i = blockIdx.x * (long)blockDim.x + threadIdx.x;
    long stride = gridDim.x * (long)blockDim.x;
    for (; i < n; i += stride) {
        unsigned k = out[i];
        float f = (k == INIT_KEY) ? 0.0f : fdecode(k);
        out[i] = __float_as_uint(f);
    }
}

// ---------------- launcher ----------------

extern "C" void kernel_launch(void* const* d_in, const int* in_sizes, int n_in,
                              void* d_out, int out_size) {
    const float* inputs = (const float*)d_in[0];
    // d_in[1] = vt_replace (unused for max pooling)
    const int*   vt_map = (const int*)d_in[2];

    long n_in_elems = in_sizes[0];                 // N_IN * C
    int  n_rows     = in_sizes[2];                 // N_IN
    int  C          = (int)(n_in_elems / n_rows);  // 64
    int  vt_out     = out_size / C;                // 262144

    const int TPB = 256;

    if (C == 64 && vt_out <= MAX_SEG && n_rows <= MAX_ROWS && (n_rows % 4) == 0) {
        int nseg = vt_out;
        int n_rows4 = n_rows / 4;

        // Zero counts + spill counter in one driver memset (graph-capturable;
        // cudaGetSymbolAddress is a host-side query, not a stream op).
        void* meta_addr = nullptr;
        cudaGetSymbolAddress(&meta_addr, g_meta);
        cudaMemsetAsync(meta_addr, 0, (size_t)(MAX_SEG + 32) * sizeof(int));

        fill_kernel<<<(n_rows4 + TPB - 1) / TPB, TPB>>>((const int4*)vt_map,
                                                        n_rows4, vt_out);

        int warps_per_block = TPB / 32;                 // 8 warps, 16 segs/block
        int segs_per_block = warps_per_block * 2;
        int gblocks = (nseg + segs_per_block - 1) / segs_per_block;
        gather_max_kernel<<<gblocks, TPB>>>((const float2*)inputs, vt_map,
                                            (float2*)d_out, nseg);
    } else {
        long out_elems = (long)out_size;
        int blocks = 148 * 16;
        init_out_kernel<<<blocks, TPB>>>((unsigned*)d_out, out_elems);
        scatter_max_kernel<<<blocks * 2, TPB>>>(inputs, vt_map,
                                                (unsigned*)d_out, n_in_elems, C, vt_out);
        fixup_kernel<<<blocks, TPB>>>((unsigned*)d_out, out_elems);
    }
}

// round 16
// speedup vs baseline: 1.0146x; 1.0146x over previous
#include <cuda_runtime.h>
#include <stdint.h>

// Segmented max pooling — bucketed gather:
//   1) memset: counts + spill counter (1 MB, driver memset)
//   2) fill:   pos = atomicAdd(count[seg]); pos<CAP -> bucket (stores
//              precomputed float2 offset row*32), else spill list (raw row)
//   3) gather: 1 warp per 2 segments, batched predicated loads (MLP=8),
//              int4 bucket loads, addressing = off + lane (no per-load IMAD),
//              __launch_bounds__(256, 8) for 64-warp residency.
//
// MEASURED LESSONS (guardrails):
//  - No single-address done-counter atomic across the big grid
//    (R6/R7: +400us, LTS same-address convoy).
//  - Plain __ldg loads; no .cs hints.
//  - MLP=8 (2 segs/warp, 256 TPB) is the sweet spot (R10/R11/R13 regressions).
//  - R15 profile: gather DRAM 61.9%, occ 59%, alu 34.8%, regs 40 ->
//    this round targets residency (launch_bounds) + address ALU (offsets).
// Fallback: generic atomic-scatter path for shapes beyond static scratch.

#define MAX_SEG   (1 << 18)   // 262144
#define MAX_ROWS  (1 << 20)   // 1048576
#define CAP        16
#define NEG_INF __int_as_float(0xff800000)

// counts[0..MAX_SEG) + spill counter in one array -> one memset clears both.
__device__ int g_meta[MAX_SEG + 32];
#define g_counts g_meta
#define SPILL_IDX MAX_SEG

__device__ int g_bucket[MAX_SEG * CAP];   // 16 MB scratch (float2 offsets)
__device__ int g_spill_rows[MAX_ROWS];

// ---------------- bucketed gather path ----------------

__global__ void fill_kernel(const int4* __restrict__ vt_map4, int n_rows4, int vt_out) {
    int i = blockIdx.x * blockDim.x + threadIdx.x;
    if (i >= n_rows4) return;
    int4 m = __ldg(&vt_map4[i]);
    int rows[4] = {4 * i, 4 * i + 1, 4 * i + 2, 4 * i + 3};
    int segs[4] = {m.x, m.y, m.z, m.w};
    #pragma unroll
    for (int k = 0; k < 4; k++) {
        int seg = segs[k];
        if (seg < 0 || seg >= vt_out) continue;
        int pos = atomicAdd(&g_counts[seg], 1);
        if (pos < CAP) {
            g_bucket[(size_t)seg * CAP + pos] = rows[k] << 5;  // row*32 float2 off
        } else {
            int s = atomicAdd(&g_counts[SPILL_IDX], 1);
            g_spill_rows[s] = rows[k];
        }
    }
}

__device__ __forceinline__ void spill_scan(float2& acc, int seg, int lane,
                                           const float2* __restrict__ in2,
                                           const int* __restrict__ vt_map) {
    int sn = g_counts[SPILL_IDX];
    for (int e = 0; e < sn; e++) {
        int row = g_spill_rows[e];
        if (__ldg(&vt_map[row]) == seg) {
            float2 a = __ldg(&in2[(size_t)row * 32 + lane]);
            acc.x = fmaxf(acc.x, a.x);
            acc.y = fmaxf(acc.y, a.y);
        }
    }
}

// One warp per TWO segments; C == 64: lane holds channels {2l, 2l+1} (float2).
// Bucket entries are precomputed float2 offsets: address = in2 + off + lane.
__global__ void __launch_bounds__(256, 8)
gather_max_kernel(const float2* __restrict__ in2,
                  const int* __restrict__ vt_map,
                  float2* __restrict__ out2, int nseg) {
    int warp = (blockIdx.x * blockDim.x + threadIdx.x) >> 5;
    int lane = threadIdx.x & 31;
    int s0 = 2 * warp;
    int s1 = s0 + 1;
    if (s0 >= nseg) return;
    bool has1 = (s1 < nseg);

    int cnt0 = __ldg(&g_counts[s0]);
    int cnt1 = has1 ? __ldg(&g_counts[s1]) : 0;
    int use0 = cnt0 < CAP ? cnt0 : CAP;
    int use1 = cnt1 < CAP ? cnt1 : CAP;

    const int4* __restrict__ b0 = (const int4*)(g_bucket + (size_t)s0 * CAP);
    const int4* __restrict__ b1 = (const int4*)(g_bucket + (size_t)s1 * CAP);

    float2 a0 = make_float2(NEG_INF, NEG_INF);
    float2 a1 = make_float2(NEG_INF, NEG_INF);
    const float2 ninf2 = make_float2(NEG_INF, NEG_INF);

    int usemax = use0 > use1 ? use0 : use1;
    for (int j = 0; j < usemax; j += 4) {
        int4 i0 = (j < use0) ? __ldg(&b0[j >> 2]) : make_int4(0, 0, 0, 0);
        int4 i1 = (j < use1) ? __ldg(&b1[j >> 2]) : make_int4(0, 0, 0, 0);

        // Issue all row loads first (predicated; NEG_INF is max-identity).
        float2 v00 = ninf2, v01 = ninf2, v02 = ninf2, v03 = ninf2;
        float2 v10 = ninf2, v11 = ninf2, v12 = ninf2, v13 = ninf2;
        if (j + 0 < use0) v00 = __ldg(&in2[i0.x + lane]);
        if (j + 1 < use0) v01 = __ldg(&in2[i0.y + lane]);
        if (j + 2 < use0) v02 = __ldg(&in2[i0.z + lane]);
        if (j + 3 < use0) v03 = __ldg(&in2[i0.w + lane]);
        if (j + 0 < use1) v10 = __ldg(&in2[i1.x + lane]);
        if (j + 1 < use1) v11 = __ldg(&in2[i1.y + lane]);
        if (j + 2 < use1) v12 = __ldg(&in2[i1.z + lane]);
        if (j + 3 < use1) v13 = __ldg(&in2[i1.w + lane]);

        a0.x = fmaxf(fmaxf(a0.x, fmaxf(v00.x, v01.x)), fmaxf(v02.x, v03.x));
        a0.y = fmaxf(fmaxf(a0.y, fmaxf(v00.y, v01.y)), fmaxf(v02.y, v03.y));
        a1.x = fmaxf(fmaxf(a1.x, fmaxf(v10.x, v11.x)), fmaxf(v12.x, v13.x));
        a1.y = fmaxf(fmaxf(a1.y, fmaxf(v10.y, v11.y)), fmaxf(v12.y, v13.y));
    }

    if (cnt0 > CAP) spill_scan(a0, s0, lane, in2, vt_map);   // statistically never
    if (cnt1 > CAP) spill_scan(a1, s1, lane, in2, vt_map);

    if (cnt0 == 0) a0 = make_float2(0.0f, 0.0f);
    if (cnt1 == 0) a1 = make_float2(0.0f, 0.0f);

    out2[(size_t)s0 * 32 + lane] = a0;
    if (has1) out2[(size_t)s1 * 32 + lane] = a1;
}

// ---------------- fallback scatter path (generic) ----------------

__device__ __forceinline__ unsigned fkey(float f) {
    unsigned b = __float_as_uint(f);
    return (b & 0x80000000u) ? ~b : (b | 0x80000000u);
}
__device__ __forceinline__ float fdecode(unsigned k) {
    unsigned b = (k & 0x80000000u) ? (k & 0x7FFFFFFFu) : ~k;
    return __uint_as_float(b);
}
#define INIT_KEY 0x007FFFFFu

__global__ void init_out_kernel(unsigned* out, long n) {
    long i = blockIdx.x * (long)blockDim.x + threadIdx.x;
    long stride = gridDim.x * (long)blockDim.x;
    for (; i < n; i += stride) out[i] = INIT_KEY;
}

__global__ void scatter_max_kernel(const float* __restrict__ in,
                                   const int* __restrict__ vt_map,
                                   unsigned* __restrict__ out,
                                   long n_total, int C, int vt_out) {
    long i = blockIdx.x * (long)blockDim.x + threadIdx.x;
    long stride = gridDim.x * (long)blockDim.x;
    for (; i < n_total; i += stride) {
        long row = i / C;
        int  c   = (int)(i - row * C);
        int seg = vt_map[row];
        if (seg < 0 || seg >= vt_out) continue;
        atomicMax(out + (size_t)seg * C + c, fkey(in[i]));
    }
}

__global__ void fixup_kernel(unsigned* __restrict__ out, long n) {
    long i = blockIdx.x * (long)blockDim.x + threadIdx.x;
    long stride = gridDim.x * (long)blockDim.x;
    for (; i < n; i += stride) {
        unsigned k = out[i];
        float f = (k == INIT_KEY) ? 0.0f : fdecode(k);
        out[i] = __float_as_uint(f);
    }
}

// ---------------- launcher ----------------

extern "C" void kernel_launch(void* const* d_in, const int* in_sizes, int n_in,
                              void* d_out, int out_size) {
    const float* inputs = (const float*)d_in[0];
    // d_in[1] = vt_replace (unused for max pooling)
    const int*   vt_map = (const int*)d_in[2];

    long n_in_elems = in_sizes[0];                 // N_IN * C
    int  n_rows     = in_sizes[2];                 // N_IN
    int  C          = (int)(n_in_elems / n_rows);  // 64
    int  vt_out     = out_size / C;                // 262144

    const int TPB = 256;

    if (C == 64 && vt_out <= MAX_SEG && n_rows <= MAX_ROWS && (n_rows % 4) == 0) {
        int nseg = vt_out;
        int n_rows4 = n_rows / 4;

        void* meta_addr = nullptr;
        cudaGetSymbolAddress(&meta_addr, g_meta);
        cudaMemsetAsync(meta_addr, 0, (size_t)(MAX_SEG + 32) * sizeof(int));

        fill_kernel<<<(n_rows4 + TPB - 1) / TPB, TPB>>>((const int4*)vt_map,
                                                        n_rows4, vt_out);

        int warps_per_block = TPB / 32;                 // 8 warps, 16 segs/block
        int segs_per_block = warps_per_block * 2;
        int gblocks = (nseg + segs_per_block - 1) / segs_per_block;
        gather_max_kernel<<<gblocks, TPB>>>((const float2*)inputs, vt_map,
                                            (float2*)d_out, nseg);
    } else {
        long out_elems = (long)out_size;
        int blocks = 148 * 16;
        init_out_kernel<<<blocks, TPB>>>((unsigned*)d_out, out_elems);
        scatter_max_kernel<<<blocks * 2, TPB>>>(inputs, vt_map,
                                                (unsigned*)d_out, n_in_elems, C, vt_out);
        fixup_kernel<<<blocks, TPB>>>((unsigned*)d_out, out_elems);
    }
}